// round 16
// baseline (speedup 1.0000x reference)
#include <cuda_runtime.h>
#include <cstdint>

#define D 128
#define MAXN 50000
#define MAXE 800000
#define SCAN_TILE 1024
#define BROW 168                 // B smem row stride (floats); conflict-free frag LDS.128
#define BCHUNK (32 * BROW)       // floats per B chunk image (5376)
#define TM 64                    // GEMM row tile
#define A_FL (TM * 36)           // A buffer floats (64*36 = 2304)
#define SMEM_FLOATS (2 * A_FL + 2 * BCHUNK + 3 * 128)

// ---------------- scratch (no allocations allowed) ----------------
__device__ float g_agg[MAXN * D];      // mean-aggregated features (tf32-rounded)
__device__ float g_x32[MAXN * D];      // tf32-rounded copy of x
__device__ float g_h[MAXN * D];        // pre-BN GEMM output
__device__ float g_h1[MAXN * D];       // post BN+ReLU layer-1 output (tf32-rounded)
__device__ float g_stats[2 * D];       // [colsum | colsumsq]
__device__ float g_wtS[2 * 8 * BCHUNK];// per-layer, per-chunk smem images of B (fragment order)
__device__ int   g_cnt[MAXN];          // zero at run start (self-restored by fill)
__device__ int   g_off[MAXN + 1];
__device__ int   g_cursor[MAXN];
__device__ int   g_csr[MAXE];
__device__ int   g_bsum[64];
__device__ int   g_boff[64];
__device__ int   g_sync1;              // zero at run start (self-restored by fill)
__device__ int   g_flag1;              // zero at run start (self-restored by fill)

__device__ __forceinline__ float to_tf32(float x) {
    uint32_t u;
    asm("cvt.rna.tf32.f32 %0, %1;" : "=r"(u) : "f"(x));
    return __uint_as_float(u);
}

// ---------------- prep: edge count + x->tf32 + weight fragment image ----------------
__global__ void prep_kernel(const float* __restrict__ x, int n4,
                            const int* __restrict__ ei, int E,
                            const float* __restrict__ W1l, const float* __restrict__ W1r,
                            const float* __restrict__ W2l, const float* __restrict__ W2r) {
    int i = blockIdx.x * blockDim.x + threadIdx.x;
    if (i < E) atomicAdd(&g_cnt[ei[E + i]], 1);      // g_cnt starts zeroed (invariant)
    if (i < 2 * 8 * BCHUNK) {
        int layer = i / (8 * BCHUNK);
        int rem = i % (8 * BCHUNK);
        int c = rem / BCHUNK;
        int rem2 = rem % BCHUNK;
        int k = rem2 / BROW;
        int j = rem2 % BROW;
        float v = 0.f;
        int jr = j % 20;
        if (j < 160 && jr < 16) {
            int q = j / 20;
            int wN = jr >> 3;
            int na = jr & 7;
            int kg = c * 32 + k;
            int n = wN * 64 + na * 8 + q;
            const float* Wl = layer ? W2l : W1l;
            const float* Wr = layer ? W2r : W1r;
            float w = (kg < 128) ? Wl[kg * 128 + n] : Wr[(kg - 128) * 128 + n];
            v = to_tf32(w);
        }
        g_wtS[i] = v;
    }
    if (i < n4) {
        float4 v = ((const float4*)x)[i];
        v.x = to_tf32(v.x); v.y = to_tf32(v.y); v.z = to_tf32(v.z); v.w = to_tf32(v.w);
        ((float4*)g_x32)[i] = v;
    }
}

// ---------------- fused 3-level scan: g_cnt -> g_off/g_cursor (one launch) ----------------
__global__ void scan_all_kernel(int N, int E, int nt) {
    __shared__ int sh[SCAN_TILE];
    __shared__ int is_last;
    int b = blockIdx.x;
    int t = threadIdx.x;
    int idx = b * SCAN_TILE + t;
    int v = (idx < N) ? g_cnt[idx] : 0;

    sh[t] = v;
    __syncthreads();
    for (int off = 512; off > 0; off >>= 1) {
        if (t < off) sh[t] += sh[t + off];
        __syncthreads();
    }
    if (t == 0) {
        g_bsum[b] = sh[0];
        __threadfence();
        int prev = atomicAdd(&g_sync1, 1);
        is_last = (prev == nt - 1);
    }
    __syncthreads();

    if (is_last) {
        if (t < 64) sh[t] = (t < nt) ? g_bsum[t] : 0;
        __syncthreads();
        if (t < 64) {
            for (int off = 1; off < 64; off <<= 1) {
                int u = (t >= off) ? sh[t - off] : 0;
                __syncthreads();
                sh[t] += u;
                __syncthreads();
            }
            if (t < nt) g_boff[t] = sh[t] - g_bsum[t];
        } else {
            for (int off = 1; off < 64; off <<= 1) { __syncthreads(); __syncthreads(); }
        }
        __syncthreads();
        if (t == 0) {
            __threadfence();
            atomicExch(&g_flag1, 1);
        }
    }
    if (t == 0) {
        while (atomicAdd(&g_flag1, 0) == 0) { }
        is_last = 0;
    }
    __syncthreads();

    sh[t] = v;
    __syncthreads();
    for (int off = 1; off < SCAN_TILE; off <<= 1) {
        int u = (t >= off) ? sh[t - off] : 0;
        __syncthreads();
        sh[t] += u;
        __syncthreads();
    }
    if (idx < N) {
        int excl = g_boff[b] + sh[t] - v;
        g_off[idx] = excl;
        g_cursor[idx] = excl;
    }
    if (b == 0 && t == 0) g_off[N] = E;
}

// ---------------- fill CSR + restore run invariants ----------------
__global__ void fill_kernel(const int* __restrict__ ei, int E, int N) {
    int gtid = blockIdx.x * blockDim.x + threadIdx.x;
    int stride = gridDim.x * blockDim.x;
    for (int e = gtid; e < E; e += stride) {
        int s = ei[e];
        int d = ei[E + e];
        int pos = atomicAdd(&g_cursor[d], 1);
        g_csr[pos] = s;
    }
    for (int i = gtid; i < N; i += stride) g_cnt[i] = 0;
    if (gtid == 0) { g_sync1 = 0; g_flag1 = 0; }
}

// ---------------- gather-mean (+ zero stats in block 0), 8-deep MLP ----------------
__global__ void gather_mean_kernel(int useInternal, int N) {
    if (blockIdx.x == 0 && threadIdx.x < 2 * D) g_stats[threadIdx.x] = 0.f;
    const float* feat = useInternal ? g_h1 : g_x32;
    int gtid = blockIdx.x * blockDim.x + threadIdx.x;
    int w = gtid >> 5;
    int lane = gtid & 31;
    if (w >= N) return;
    int beg = g_off[w];
    int end = g_off[w + 1];
    float4 acc = make_float4(0.f, 0.f, 0.f, 0.f);
    int j = beg;
    for (; j + 8 <= end; j += 8) {
        int s0 = __ldg(&g_csr[j + 0]);
        int s1 = __ldg(&g_csr[j + 1]);
        int s2 = __ldg(&g_csr[j + 2]);
        int s3 = __ldg(&g_csr[j + 3]);
        int s4 = __ldg(&g_csr[j + 4]);
        int s5 = __ldg(&g_csr[j + 5]);
        int s6 = __ldg(&g_csr[j + 6]);
        int s7 = __ldg(&g_csr[j + 7]);
        float4 v0 = ((const float4*)(feat + (size_t)s0 * D))[lane];
        float4 v1 = ((const float4*)(feat + (size_t)s1 * D))[lane];
        float4 v2 = ((const float4*)(feat + (size_t)s2 * D))[lane];
        float4 v3 = ((const float4*)(feat + (size_t)s3 * D))[lane];
        float4 v4 = ((const float4*)(feat + (size_t)s4 * D))[lane];
        float4 v5 = ((const float4*)(feat + (size_t)s5 * D))[lane];
        float4 v6 = ((const float4*)(feat + (size_t)s6 * D))[lane];
        float4 v7 = ((const float4*)(feat + (size_t)s7 * D))[lane];
        acc.x += (v0.x + v1.x) + (v2.x + v3.x) + (v4.x + v5.x) + (v6.x + v7.x);
        acc.y += (v0.y + v1.y) + (v2.y + v3.y) + (v4.y + v5.y) + (v6.y + v7.y);
        acc.z += (v0.z + v1.z) + (v2.z + v3.z) + (v4.z + v5.z) + (v6.z + v7.z);
        acc.w += (v0.w + v1.w) + (v2.w + v3.w) + (v4.w + v5.w) + (v6.w + v7.w);
    }
    for (; j + 4 <= end; j += 4) {
        int s0 = __ldg(&g_csr[j + 0]);
        int s1 = __ldg(&g_csr[j + 1]);
        int s2 = __ldg(&g_csr[j + 2]);
        int s3 = __ldg(&g_csr[j + 3]);
        float4 v0 = ((const float4*)(feat + (size_t)s0 * D))[lane];
        float4 v1 = ((const float4*)(feat + (size_t)s1 * D))[lane];
        float4 v2 = ((const float4*)(feat + (size_t)s2 * D))[lane];
        float4 v3 = ((const float4*)(feat + (size_t)s3 * D))[lane];
        acc.x += v0.x + v1.x + v2.x + v3.x;
        acc.y += v0.y + v1.y + v2.y + v3.y;
        acc.z += v0.z + v1.z + v2.z + v3.z;
        acc.w += v0.w + v1.w + v2.w + v3.w;
    }
    for (; j < end; j++) {
        int s = __ldg(&g_csr[j]);
        float4 v = ((const float4*)(feat + (size_t)s * D))[lane];
        acc.x += v.x; acc.y += v.y; acc.z += v.z; acc.w += v.w;
    }
    float sc = 1.f / (float)max(end - beg, 1);
    acc.x = to_tf32(acc.x * sc);
    acc.y = to_tf32(acc.y * sc);
    acc.z = to_tf32(acc.z * sc);
    acc.w = to_tf32(acc.w * sc);
    ((float4*)(g_agg + (size_t)w * D))[lane] = acc;
}

// ---------------- mma.sync tf32 GEMM: 64x128 tile, 3 CTAs/SM, cp.async pipelined ----------------
// 256 threads = 8 warps (4 M x 2 N); warp tile 16x64 (1 m16 x 8 n8). K=256 in 8 chunks of 32.
__global__ __launch_bounds__(256, 3) void gemm_mma(
    int layer, const float* __restrict__ bias, int M)
{
    extern __shared__ float sm[];
    float* Asd = sm;                    // 2 * A_FL
    float* Btd = sm + 2 * A_FL;         // 2 * BCHUNK
    float* sbias = Btd + 2 * BCHUNK;    // 128
    float* ss = sbias + 128;            // 128
    float* sq = ss + 128;               // 128

    int tid = threadIdx.x;
    int lane = tid & 31;
    int wid = tid >> 5;
    int warpM = wid & 3;
    int warpN = wid >> 2;
    int row0 = blockIdx.x * TM;
    int q = lane >> 2;
    int r4 = lane & 3;

    const float* srcLo = g_agg;
    const float* srcHi = layer ? g_h1 : g_x32;
    const float* wbase = g_wtS + (size_t)layer * 8 * BCHUNK;

    if (tid < 128) {
        sbias[tid] = bias[tid];
        ss[tid] = 0.f;
        sq[tid] = 0.f;
    }

    uint32_t As_sh = (uint32_t)__cvta_generic_to_shared(Asd);
    uint32_t Bt_sh = (uint32_t)__cvta_generic_to_shared(Btd);

    auto issue = [&](int c, int buf) {
        int k0 = c * 32;
        const float* Asrc = (k0 < 128) ? srcLo : srcHi;
        int koff = k0 & 127;
        // A chunk: 64x32 floats = 512 float4, 2/thread
#pragma unroll
        for (int i = 0; i < 2; i++) {
            int idx = tid + i * 256;
            int r = idx >> 3;
            int cc = (idx & 7) * 4;
            int gr = row0 + r;
            int valid = (gr < M);
            const float* src = Asrc + (size_t)(valid ? gr : 0) * D + koff + cc;
            uint32_t dst = As_sh + (buf * A_FL + r * 36 + cc) * 4;
            int sz = valid ? 16 : 0;
            asm volatile("cp.async.cg.shared.global [%0], [%1], 16, %2;"
                         :: "r"(dst), "l"(src), "r"(sz));
        }
        const float* Bsrc = wbase + (size_t)c * BCHUNK;
#pragma unroll
        for (int i = 0; i < 6; i++) {
            int idx = tid + i * 256;
            if (idx < BCHUNK / 4) {
                uint32_t dst = Bt_sh + (buf * BCHUNK) * 4 + idx * 16;
                asm volatile("cp.async.cg.shared.global [%0], [%1], 16;"
                             :: "r"(dst), "l"(Bsrc + idx * 4));
            }
        }
    };

    float acc[8][4];
#pragma unroll
    for (int na = 0; na < 8; na++)
#pragma unroll
        for (int j = 0; j < 4; j++) acc[na][j] = 0.f;

    int bj = q * 20 + warpN * 8;

    issue(0, 0);
    asm volatile("cp.async.commit_group;");

    for (int c = 0; c < 8; c++) {
        int buf = c & 1;
        if (c + 1 < 8) {
            issue(c + 1, buf ^ 1);
            asm volatile("cp.async.commit_group;");
            asm volatile("cp.async.wait_group 1;");
        } else {
            asm volatile("cp.async.wait_group 0;");
        }
        __syncthreads();

        const float* Ab = Asd + buf * A_FL;
        const float* Bb = Btd + buf * BCHUNK;
#pragma unroll
        for (int kk = 0; kk < 32; kk += 8) {
            const float* p0 = Bb + (kk + r4) * BROW + bj;
            const float* p1 = p0 + 4 * BROW;
            float4 b0lo = *(const float4*)p0;
            float4 b0hi = *(const float4*)(p0 + 4);
            float4 b1lo = *(const float4*)p1;
            float4 b1hi = *(const float4*)(p1 + 4);
            float b0arr[8] = {b0lo.x, b0lo.y, b0lo.z, b0lo.w, b0hi.x, b0hi.y, b0hi.z, b0hi.w};
            float b1arr[8] = {b1lo.x, b1lo.y, b1lo.z, b1lo.w, b1hi.x, b1hi.y, b1hi.z, b1hi.w};
            int r = warpM * 16 + q;
            int ac = kk + r4;
            float a0 = Ab[r * 36 + ac];
            float a1 = Ab[(r + 8) * 36 + ac];
            float a2 = Ab[r * 36 + ac + 4];
            float a3 = Ab[(r + 8) * 36 + ac + 4];
#pragma unroll
            for (int na = 0; na < 8; na++) {
                uint32_t b0 = __float_as_uint(b0arr[na]);
                uint32_t b1 = __float_as_uint(b1arr[na]);
                asm volatile(
                    "mma.sync.aligned.m16n8k8.row.col.f32.tf32.tf32.f32 "
                    "{%0,%1,%2,%3}, {%4,%5,%6,%7}, {%8,%9}, {%0,%1,%2,%3};"
                    : "+f"(acc[na][0]), "+f"(acc[na][1]),
                      "+f"(acc[na][2]), "+f"(acc[na][3])
                    : "r"(__float_as_uint(a0)), "r"(__float_as_uint(a1)),
                      "r"(__float_as_uint(a2)), "r"(__float_as_uint(a3)),
                      "r"(b0), "r"(b1));
            }
        }
        __syncthreads();
    }

    // epilogue: +bias, store h, accumulate column stats
    int r0 = row0 + warpM * 16 + q;
    int c0 = warpN * 64 + 2 * r4;
#pragma unroll
    for (int na = 0; na < 8; na++) {
        int col = c0 + na * 8;
        float s0 = 0.f, s1 = 0.f, q0 = 0.f, q1 = 0.f;
        if (r0 < M) {
            float o0 = acc[na][0] + sbias[col];
            float o1 = acc[na][1] + sbias[col + 1];
            *(float2*)&g_h[(size_t)r0 * D + col] = make_float2(o0, o1);
            s0 += o0; s1 += o1; q0 += o0 * o0; q1 += o1 * o1;
        }
        if (r0 + 8 < M) {
            float o0 = acc[na][2] + sbias[col];
            float o1 = acc[na][3] + sbias[col + 1];
            *(float2*)&g_h[(size_t)(r0 + 8) * D + col] = make_float2(o0, o1);
            s0 += o0; s1 += o1; q0 += o0 * o0; q1 += o1 * o1;
        }
        atomicAdd(&ss[col], s0);
        atomicAdd(&ss[col + 1], s1);
        atomicAdd(&sq[col], q0);
        atomicAdd(&sq[col + 1], q1);
    }
    __syncthreads();
    if (tid < 128) {
        atomicAdd(&g_stats[tid], ss[tid]);
        atomicAdd(&g_stats[D + tid], sq[tid]);
    }
}

// ---------------- apply BN + ReLU (layer 1); scale/shift computed per block ----------------
__global__ void apply_relu_kernel(const float* __restrict__ gamma,
                                  const float* __restrict__ beta, int M) {
    __shared__ float sc_s[D], sh_s[D];
    int tid = threadIdx.x;
    if (tid < D) {
        float inv = 1.f / (float)M;
        float mean = g_stats[tid] * inv;
        float var = g_stats[D + tid] * inv - mean * mean;
        float s = gamma[tid] * rsqrtf(var + 1e-5f);
        sc_s[tid] = s;
        sh_s[tid] = beta[tid] - mean * s;
    }
    __syncthreads();
    int i = blockIdx.x * blockDim.x + tid;
    if (i >= M * (D / 4)) return;
    int c4 = i & (D / 4 - 1);
    float4 v = ((const float4*)g_h)[i];
    float4 sc = *(const float4*)&sc_s[c4 * 4];
    float4 sh = *(const float4*)&sh_s[c4 * 4];
    float4 o;
    o.x = to_tf32(fmaxf(fmaf(v.x, sc.x, sh.x), 0.f));
    o.y = to_tf32(fmaxf(fmaf(v.y, sc.y, sh.y), 0.f));
    o.z = to_tf32(fmaxf(fmaf(v.z, sc.z, sh.z), 0.f));
    o.w = to_tf32(fmaxf(fmaf(v.w, sc.w, sh.w), 0.f));
    ((float4*)g_h1)[i] = o;
}

// ---------------- apply BN + residual + ReLU (layer 2); scale/shift per block ----------------
__global__ void final_kernel(const float* __restrict__ gamma,
                             const float* __restrict__ beta,
                             const float* __restrict__ xin, float* __restrict__ out, int M) {
    __shared__ float sc_s[D], sh_s[D];
    int tid = threadIdx.x;
    if (tid < D) {
        float inv = 1.f / (float)M;
        float mean = g_stats[tid] * inv;
        float var = g_stats[D + tid] * inv - mean * mean;
        float s = gamma[tid] * rsqrtf(var + 1e-5f);
        sc_s[tid] = s;
        sh_s[tid] = beta[tid] - mean * s;
    }
    __syncthreads();
    int i = blockIdx.x * blockDim.x + tid;
    if (i >= M * (D / 4)) return;
    int c4 = i & (D / 4 - 1);
    float4 v = ((const float4*)g_h)[i];
    float4 xv = ((const float4*)xin)[i];
    float4 sc = *(const float4*)&sc_s[c4 * 4];
    float4 sh = *(const float4*)&sh_s[c4 * 4];
    float4 o;
    o.x = fmaxf(fmaf(v.x, sc.x, sh.x) + xv.x, 0.f);
    o.y = fmaxf(fmaf(v.y, sc.y, sh.y) + xv.y, 0.f);
    o.z = fmaxf(fmaf(v.z, sc.z, sh.z) + xv.z, 0.f);
    o.w = fmaxf(fmaf(v.w, sc.w, sh.w) + xv.w, 0.f);
    ((float4*)out)[i] = o;
}

extern "C" void kernel_launch(void* const* d_in, const int* in_sizes, int n_in,
                              void* d_out, int out_size) {
    const float* x       = (const float*)d_in[0];
    const int*   ei      = (const int*)d_in[1];   // int32 edge_index
    const float* W1l     = (const float*)d_in[2];
    const float* b1      = (const float*)d_in[3];
    const float* W1r     = (const float*)d_in[4];
    const float* g1      = (const float*)d_in[5];
    const float* bt1     = (const float*)d_in[6];
    const float* W2l     = (const float*)d_in[7];
    const float* b2      = (const float*)d_in[8];
    const float* W2r     = (const float*)d_in[9];
    const float* g2      = (const float*)d_in[10];
    const float* bt2     = (const float*)d_in[11];
    float* out = (float*)d_out;

    int M = in_sizes[0] / D;
    int E = in_sizes[1] / 2;
    int n4 = M * (D / 4);
    int eb = (E + 255) / 256;
    int nt = (M + SCAN_TILE - 1) / SCAN_TILE;
    int prep_blocks = (n4 + 255) / 256;
    if (prep_blocks < eb) prep_blocks = eb;
    int gather_blocks = (M + 7) / 8;
    int gemm_blocks = (M + TM - 1) / TM;
    int ew_blocks = (n4 + 255) / 256;
    int smem_bytes = SMEM_FLOATS * 4;   // 62,976 B

    static int attr_set = 0;
    if (!attr_set) {
        cudaFuncSetAttribute(gemm_mma, cudaFuncAttributeMaxDynamicSharedMemorySize, smem_bytes);
        attr_set = 1;
    }

    // ---- prep (+edge count) + fused scan + fill (once) ----
    prep_kernel<<<prep_blocks, 256>>>(x, n4, ei, E, W1l, W1r, W2l, W2r);
    scan_all_kernel<<<nt, SCAN_TILE>>>(M, E, nt);
    fill_kernel<<<eb, 256>>>(ei, E, M);

    // ---- layer 1 ----
    gather_mean_kernel<<<gather_blocks, 256>>>(0, M);
    gemm_mma<<<gemm_blocks, 256, smem_bytes>>>(0, b1, M);
    apply_relu_kernel<<<ew_blocks, 256>>>(g1, bt1, M);

    // ---- layer 2 ----
    gather_mean_kernel<<<gather_blocks, 256>>>(1, M);
    gemm_mma<<<gemm_blocks, 256, smem_bytes>>>(1, b2, M);
    final_kernel<<<ew_blocks, 256>>>(g2, bt2, x, out, M);
}

// round 17
// speedup vs baseline: 1.0769x; 1.0769x over previous
#include <cuda_runtime.h>
#include <cstdint>

#define D 128
#define MAXN 50000
#define MAXE 800000
#define SCAN_TILE 1024
#define BROW 168                 // B smem row stride (floats); conflict-free frag LDS.128
#define BCHUNK (32 * BROW)       // floats per B chunk image (5376)
#define A_FL 4608                // A buffer floats (128*36)
#define SMEM_FLOATS (2 * A_FL + 2 * BCHUNK + 3 * 128)

// ---------------- scratch (no allocations allowed) ----------------
__device__ float g_agg[MAXN * D];      // mean-aggregated features (tf32-rounded)
__device__ float g_x32[MAXN * D];      // tf32-rounded copy of x
__device__ float g_h[MAXN * D];        // pre-BN GEMM output
__device__ float g_h1[MAXN * D];       // post BN+ReLU layer-1 output (tf32-rounded)
__device__ float g_stats[2 * D];       // [colsum | colsumsq]
__device__ float g_wtS[2 * 8 * BCHUNK];// per-layer, per-chunk smem images of B (fragment order)
__device__ int   g_cnt[MAXN];          // zero at run start (self-restored by fill)
__device__ int   g_off[MAXN + 1];
__device__ int   g_cursor[MAXN];
__device__ int   g_csr[MAXE];
__device__ int   g_bsum[64];
__device__ int   g_boff[64];
__device__ int   g_sync1;              // zero at run start (self-restored by fill)
__device__ int   g_flag1;              // zero at run start (self-restored by fill)

__device__ __forceinline__ float to_tf32(float x) {
    uint32_t u;
    asm("cvt.rna.tf32.f32 %0, %1;" : "=r"(u) : "f"(x));
    return __uint_as_float(u);
}

// ---------------- prep: edge count + x->tf32 + weight fragment image ----------------
__global__ void prep_kernel(const float* __restrict__ x, int n4,
                            const int* __restrict__ ei, int E,
                            const float* __restrict__ W1l, const float* __restrict__ W1r,
                            const float* __restrict__ W2l, const float* __restrict__ W2r) {
    int i = blockIdx.x * blockDim.x + threadIdx.x;
    if (i < E) atomicAdd(&g_cnt[ei[E + i]], 1);      // g_cnt starts zeroed (invariant)
    if (i < 2 * 8 * BCHUNK) {
        int layer = i / (8 * BCHUNK);
        int rem = i % (8 * BCHUNK);
        int c = rem / BCHUNK;
        int rem2 = rem % BCHUNK;
        int k = rem2 / BROW;
        int j = rem2 % BROW;
        float v = 0.f;
        int jr = j % 20;
        if (j < 160 && jr < 16) {
            int q = j / 20;
            int wN = jr >> 3;
            int na = jr & 7;
            int kg = c * 32 + k;
            int n = wN * 64 + na * 8 + q;
            const float* Wl = layer ? W2l : W1l;
            const float* Wr = layer ? W2r : W1r;
            float w = (kg < 128) ? Wl[kg * 128 + n] : Wr[(kg - 128) * 128 + n];
            v = to_tf32(w);
        }
        g_wtS[i] = v;
    }
    if (i < n4) {
        float4 v = ((const float4*)x)[i];
        v.x = to_tf32(v.x); v.y = to_tf32(v.y); v.z = to_tf32(v.z); v.w = to_tf32(v.w);
        ((float4*)g_x32)[i] = v;
    }
}

// ---------------- fused 3-level scan: g_cnt -> g_off/g_cursor (one launch) ----------------
__global__ void scan_all_kernel(int N, int E, int nt) {
    __shared__ int sh[SCAN_TILE];
    __shared__ int is_last;
    int b = blockIdx.x;
    int t = threadIdx.x;
    int idx = b * SCAN_TILE + t;
    int v = (idx < N) ? g_cnt[idx] : 0;

    sh[t] = v;
    __syncthreads();
    for (int off = 512; off > 0; off >>= 1) {
        if (t < off) sh[t] += sh[t + off];
        __syncthreads();
    }
    if (t == 0) {
        g_bsum[b] = sh[0];
        __threadfence();
        int prev = atomicAdd(&g_sync1, 1);
        is_last = (prev == nt - 1);
    }
    __syncthreads();

    if (is_last) {
        if (t < 64) sh[t] = (t < nt) ? g_bsum[t] : 0;
        __syncthreads();
        if (t < 64) {
            for (int off = 1; off < 64; off <<= 1) {
                int u = (t >= off) ? sh[t - off] : 0;
                __syncthreads();
                sh[t] += u;
                __syncthreads();
            }
            if (t < nt) g_boff[t] = sh[t] - g_bsum[t];
        } else {
            for (int off = 1; off < 64; off <<= 1) { __syncthreads(); __syncthreads(); }
        }
        __syncthreads();
        if (t == 0) {
            __threadfence();
            atomicExch(&g_flag1, 1);
        }
    }
    if (t == 0) {
        while (atomicAdd(&g_flag1, 0) == 0) { }
        is_last = 0;
    }
    __syncthreads();

    sh[t] = v;
    __syncthreads();
    for (int off = 1; off < SCAN_TILE; off <<= 1) {
        int u = (t >= off) ? sh[t - off] : 0;
        __syncthreads();
        sh[t] += u;
        __syncthreads();
    }
    if (idx < N) {
        int excl = g_boff[b] + sh[t] - v;
        g_off[idx] = excl;
        g_cursor[idx] = excl;
    }
    if (b == 0 && t == 0) g_off[N] = E;
}

// ---------------- fill CSR + restore run invariants ----------------
__global__ void fill_kernel(const int* __restrict__ ei, int E, int N) {
    int gtid = blockIdx.x * blockDim.x + threadIdx.x;
    int stride = gridDim.x * blockDim.x;
    for (int e = gtid; e < E; e += stride) {
        int s = ei[e];
        int d = ei[E + e];
        int pos = atomicAdd(&g_cursor[d], 1);
        g_csr[pos] = s;
    }
    for (int i = gtid; i < N; i += stride) g_cnt[i] = 0;
    if (gtid == 0) { g_sync1 = 0; g_flag1 = 0; }
}

// ---------------- gather-mean (+ zero stats in block 0) ----------------
__global__ void gather_mean_kernel(int useInternal, int N) {
    if (blockIdx.x == 0 && threadIdx.x < 2 * D) g_stats[threadIdx.x] = 0.f;
    const float* feat = useInternal ? g_h1 : g_x32;
    int gtid = blockIdx.x * blockDim.x + threadIdx.x;
    int w = gtid >> 5;
    int lane = gtid & 31;
    if (w >= N) return;
    int beg = g_off[w];
    int end = g_off[w + 1];
    float4 acc = make_float4(0.f, 0.f, 0.f, 0.f);
    int j = beg;
    for (; j + 4 <= end; j += 4) {
        int s0 = __ldg(&g_csr[j + 0]);
        int s1 = __ldg(&g_csr[j + 1]);
        int s2 = __ldg(&g_csr[j + 2]);
        int s3 = __ldg(&g_csr[j + 3]);
        float4 v0 = ((const float4*)(feat + (size_t)s0 * D))[lane];
        float4 v1 = ((const float4*)(feat + (size_t)s1 * D))[lane];
        float4 v2 = ((const float4*)(feat + (size_t)s2 * D))[lane];
        float4 v3 = ((const float4*)(feat + (size_t)s3 * D))[lane];
        acc.x += v0.x + v1.x + v2.x + v3.x;
        acc.y += v0.y + v1.y + v2.y + v3.y;
        acc.z += v0.z + v1.z + v2.z + v3.z;
        acc.w += v0.w + v1.w + v2.w + v3.w;
    }
    for (; j < end; j++) {
        int s = __ldg(&g_csr[j]);
        float4 v = ((const float4*)(feat + (size_t)s * D))[lane];
        acc.x += v.x; acc.y += v.y; acc.z += v.z; acc.w += v.w;
    }
    float sc = 1.f / (float)max(end - beg, 1);
    acc.x = to_tf32(acc.x * sc);
    acc.y = to_tf32(acc.y * sc);
    acc.z = to_tf32(acc.z * sc);
    acc.w = to_tf32(acc.w * sc);
    ((float4*)(g_agg + (size_t)w * D))[lane] = acc;
}

// ---------------- mma.sync tf32 GEMM: cp.async double-buffered A+B, fragment B ----------------
// CTA 128x128, 256 threads = 8 warps (4 M x 2 N). K=256 in 8 chunks of 32.
__global__ __launch_bounds__(256) void gemm_mma(
    int layer, const float* __restrict__ bias, int M)
{
    extern __shared__ float sm[];
    float* Asd = sm;                    // 2 * A_FL
    float* Btd = sm + 2 * A_FL;         // 2 * BCHUNK
    float* sbias = Btd + 2 * BCHUNK;    // 128
    float* ss = sbias + 128;            // 128
    float* sq = ss + 128;               // 128

    int tid = threadIdx.x;
    int lane = tid & 31;
    int wid = tid >> 5;
    int warpM = wid & 3;
    int warpN = wid >> 2;
    int row0 = blockIdx.x * 128;
    int q = lane >> 2;
    int r4 = lane & 3;

    const float* srcLo = g_agg;
    const float* srcHi = layer ? g_h1 : g_x32;
    const float* wbase = g_wtS + (size_t)layer * 8 * BCHUNK;

    if (tid < 128) {
        sbias[tid] = bias[tid];
        ss[tid] = 0.f;
        sq[tid] = 0.f;
    }

    uint32_t As_sh = (uint32_t)__cvta_generic_to_shared(Asd);
    uint32_t Bt_sh = (uint32_t)__cvta_generic_to_shared(Btd);

    auto issue = [&](int c, int buf) {
        int k0 = c * 32;
        const float* Asrc = (k0 < 128) ? srcLo : srcHi;
        int koff = k0 & 127;
#pragma unroll
        for (int i = 0; i < 4; i++) {
            int idx = tid + i * 256;
            int r = idx >> 3;
            int cc = (idx & 7) * 4;
            int gr = row0 + r;
            int valid = (gr < M);
            const float* src = Asrc + (size_t)(valid ? gr : 0) * D + koff + cc;
            uint32_t dst = As_sh + (buf * A_FL + r * 36 + cc) * 4;
            int sz = valid ? 16 : 0;
            asm volatile("cp.async.cg.shared.global [%0], [%1], 16, %2;"
                         :: "r"(dst), "l"(src), "r"(sz));
        }
        const float* Bsrc = wbase + (size_t)c * BCHUNK;
#pragma unroll
        for (int i = 0; i < 6; i++) {
            int idx = tid + i * 256;
            if (idx < BCHUNK / 4) {
                uint32_t dst = Bt_sh + (buf * BCHUNK) * 4 + idx * 16;
                asm volatile("cp.async.cg.shared.global [%0], [%1], 16;"
                             :: "r"(dst), "l"(Bsrc + idx * 4));
            }
        }
    };

    float acc[2][8][4];
#pragma unroll
    for (int ma = 0; ma < 2; ma++)
#pragma unroll
        for (int na = 0; na < 8; na++)
#pragma unroll
            for (int j = 0; j < 4; j++) acc[ma][na][j] = 0.f;

    int bj = q * 20 + warpN * 8;

    issue(0, 0);
    asm volatile("cp.async.commit_group;");

    for (int c = 0; c < 8; c++) {
        int buf = c & 1;
        if (c + 1 < 8) {
            issue(c + 1, buf ^ 1);
            asm volatile("cp.async.commit_group;");
            asm volatile("cp.async.wait_group 1;");
        } else {
            asm volatile("cp.async.wait_group 0;");
        }
        __syncthreads();

        const float* Ab = Asd + buf * A_FL;
        const float* Bb = Btd + buf * BCHUNK;
#pragma unroll
        for (int kk = 0; kk < 32; kk += 8) {
            const float* p0 = Bb + (kk + r4) * BROW + bj;
            const float* p1 = p0 + 4 * BROW;
            float4 b0lo = *(const float4*)p0;
            float4 b0hi = *(const float4*)(p0 + 4);
            float4 b1lo = *(const float4*)p1;
            float4 b1hi = *(const float4*)(p1 + 4);
            float b0arr[8] = {b0lo.x, b0lo.y, b0lo.z, b0lo.w, b0hi.x, b0hi.y, b0hi.z, b0hi.w};
            float b1arr[8] = {b1lo.x, b1lo.y, b1lo.z, b1lo.w, b1hi.x, b1hi.y, b1hi.z, b1hi.w};
            float a[2][4];
            int ar = warpM * 32 + q;
            int ac = kk + r4;
#pragma unroll
            for (int ma = 0; ma < 2; ma++) {
                int r = ar + ma * 16;
                a[ma][0] = Ab[r * 36 + ac];
                a[ma][1] = Ab[(r + 8) * 36 + ac];
                a[ma][2] = Ab[r * 36 + ac + 4];
                a[ma][3] = Ab[(r + 8) * 36 + ac + 4];
            }
#pragma unroll
            for (int na = 0; na < 8; na++) {
                uint32_t b0 = __float_as_uint(b0arr[na]);
                uint32_t b1 = __float_as_uint(b1arr[na]);
#pragma unroll
                for (int ma = 0; ma < 2; ma++) {
                    asm volatile(
                        "mma.sync.aligned.m16n8k8.row.col.f32.tf32.tf32.f32 "
                        "{%0,%1,%2,%3}, {%4,%5,%6,%7}, {%8,%9}, {%0,%1,%2,%3};"
                        : "+f"(acc[ma][na][0]), "+f"(acc[ma][na][1]),
                          "+f"(acc[ma][na][2]), "+f"(acc[ma][na][3])
                        : "r"(__float_as_uint(a[ma][0])), "r"(__float_as_uint(a[ma][1])),
                          "r"(__float_as_uint(a[ma][2])), "r"(__float_as_uint(a[ma][3])),
                          "r"(b0), "r"(b1));
                }
            }
        }
        __syncthreads();
    }

    int r0 = row0 + warpM * 32 + q;
    int c0 = warpN * 64 + 2 * r4;
#pragma unroll
    for (int na = 0; na < 8; na++) {
        int col = c0 + na * 8;
        float s0 = 0.f, s1 = 0.f, q0 = 0.f, q1 = 0.f;
#pragma unroll
        for (int ma = 0; ma < 2; ma++) {
            int gr = r0 + ma * 16;
            if (gr < M) {
                float o0 = acc[ma][na][0] + sbias[col];
                float o1 = acc[ma][na][1] + sbias[col + 1];
                *(float2*)&g_h[(size_t)gr * D + col] = make_float2(o0, o1);
                s0 += o0; s1 += o1; q0 += o0 * o0; q1 += o1 * o1;
            }
            if (gr + 8 < M) {
                float o0 = acc[ma][na][2] + sbias[col];
                float o1 = acc[ma][na][3] + sbias[col + 1];
                *(float2*)&g_h[(size_t)(gr + 8) * D + col] = make_float2(o0, o1);
                s0 += o0; s1 += o1; q0 += o0 * o0; q1 += o1 * o1;
            }
        }
        atomicAdd(&ss[col], s0);
        atomicAdd(&ss[col + 1], s1);
        atomicAdd(&sq[col], q0);
        atomicAdd(&sq[col + 1], q1);
    }
    __syncthreads();
    if (tid < 128) {
        atomicAdd(&g_stats[tid], ss[tid]);
        atomicAdd(&g_stats[D + tid], sq[tid]);
    }
}

// ---------------- apply BN + ReLU (layer 1); scale/shift computed per block ----------------
__global__ void apply_relu_kernel(const float* __restrict__ gamma,
                                  const float* __restrict__ beta, int M) {
    __shared__ float sc_s[D], sh_s[D];
    int tid = threadIdx.x;
    if (tid < D) {
        float inv = 1.f / (float)M;
        float mean = g_stats[tid] * inv;
        float var = g_stats[D + tid] * inv - mean * mean;
        float s = gamma[tid] * rsqrtf(var + 1e-5f);
        sc_s[tid] = s;
        sh_s[tid] = beta[tid] - mean * s;
    }
    __syncthreads();
    int i = blockIdx.x * blockDim.x + tid;
    if (i >= M * (D / 4)) return;
    int c4 = i & (D / 4 - 1);
    float4 v = ((const float4*)g_h)[i];
    float4 sc = *(const float4*)&sc_s[c4 * 4];
    float4 sh = *(const float4*)&sh_s[c4 * 4];
    float4 o;
    o.x = to_tf32(fmaxf(fmaf(v.x, sc.x, sh.x), 0.f));
    o.y = to_tf32(fmaxf(fmaf(v.y, sc.y, sh.y), 0.f));
    o.z = to_tf32(fmaxf(fmaf(v.z, sc.z, sh.z), 0.f));
    o.w = to_tf32(fmaxf(fmaf(v.w, sc.w, sh.w), 0.f));
    ((float4*)g_h1)[i] = o;
}

// ---------------- apply BN + residual + ReLU (layer 2); scale/shift per block ----------------
__global__ void final_kernel(const float* __restrict__ gamma,
                             const float* __restrict__ beta,
                             const float* __restrict__ xin, float* __restrict__ out, int M) {
    __shared__ float sc_s[D], sh_s[D];
    int tid = threadIdx.x;
    if (tid < D) {
        float inv = 1.f / (float)M;
        float mean = g_stats[tid] * inv;
        float var = g_stats[D + tid] * inv - mean * mean;
        float s = gamma[tid] * rsqrtf(var + 1e-5f);
        sc_s[tid] = s;
        sh_s[tid] = beta[tid] - mean * s;
    }
    __syncthreads();
    int i = blockIdx.x * blockDim.x + tid;
    if (i >= M * (D / 4)) return;
    int c4 = i & (D / 4 - 1);
    float4 v = ((const float4*)g_h)[i];
    float4 xv = ((const float4*)xin)[i];
    float4 sc = *(const float4*)&sc_s[c4 * 4];
    float4 sh = *(const float4*)&sh_s[c4 * 4];
    float4 o;
    o.x = fmaxf(fmaf(v.x, sc.x, sh.x) + xv.x, 0.f);
    o.y = fmaxf(fmaf(v.y, sc.y, sh.y) + xv.y, 0.f);
    o.z = fmaxf(fmaf(v.z, sc.z, sh.z) + xv.z, 0.f);
    o.w = fmaxf(fmaf(v.w, sc.w, sh.w) + xv.w, 0.f);
    ((float4*)out)[i] = o;
}

extern "C" void kernel_launch(void* const* d_in, const int* in_sizes, int n_in,
                              void* d_out, int out_size) {
    const float* x       = (const float*)d_in[0];
    const int*   ei      = (const int*)d_in[1];   // int32 edge_index
    const float* W1l     = (const float*)d_in[2];
    const float* b1      = (const float*)d_in[3];
    const float* W1r     = (const float*)d_in[4];
    const float* g1      = (const float*)d_in[5];
    const float* bt1     = (const float*)d_in[6];
    const float* W2l     = (const float*)d_in[7];
    const float* b2      = (const float*)d_in[8];
    const float* W2r     = (const float*)d_in[9];
    const float* g2      = (const float*)d_in[10];
    const float* bt2     = (const float*)d_in[11];
    float* out = (float*)d_out;

    int M = in_sizes[0] / D;
    int E = in_sizes[1] / 2;
    int n4 = M * (D / 4);
    int eb = (E + 255) / 256;
    int nt = (M + SCAN_TILE - 1) / SCAN_TILE;
    int prep_blocks = (n4 + 255) / 256;
    if (prep_blocks < eb) prep_blocks = eb;
    int gather_blocks = (M + 7) / 8;
    int gemm_blocks = (M + 127) / 128;
    int ew_blocks = (n4 + 255) / 256;
    int smem_bytes = SMEM_FLOATS * 4;   // 81,408 B

    static int attr_set = 0;
    if (!attr_set) {
        cudaFuncSetAttribute(gemm_mma, cudaFuncAttributeMaxDynamicSharedMemorySize, smem_bytes);
        attr_set = 1;
    }

    // ---- prep (+edge count) + fused scan + fill (once) ----
    prep_kernel<<<prep_blocks, 256>>>(x, n4, ei, E, W1l, W1r, W2l, W2r);
    scan_all_kernel<<<nt, SCAN_TILE>>>(M, E, nt);
    fill_kernel<<<eb, 256>>>(ei, E, M);

    // ---- layer 1 ----
    gather_mean_kernel<<<gather_blocks, 256>>>(0, M);
    gemm_mma<<<gemm_blocks, 256, smem_bytes>>>(0, b1, M);
    apply_relu_kernel<<<ew_blocks, 256>>>(g1, bt1, M);

    // ---- layer 2 ----
    gather_mean_kernel<<<gather_blocks, 256>>>(1, M);
    gemm_mma<<<gemm_blocks, 256, smem_bytes>>>(1, b2, M);
    final_kernel<<<ew_blocks, 256>>>(g2, bt2, x, out, M);
}